// round 11
// baseline (speedup 1.0000x reference)
#include <cuda_runtime.h>
#include <cuda_bf16.h>

#define B_DIM 64
#define J_DIM 24
#define T_DIM 2048
#define T4 (T_DIM / 4)
#define LAMBDA_VEL 0.2
#define LAMBDA_FOOT 0.1
#define CONTACT_THRESH 0.05f

#define GRID_BLOCKS 1152   // 1152*256 = 294912 threads; n4/threads = 16 exactly
#define NTHREADS 256
#define MAIN_ITERS 16

// accumulators: [0]=recon, [1]=vel, [2]=foot_loss, [3]=cw_sum  (zero-init, reset by last block)
__device__ double g_acc[4];
__device__ unsigned int g_done;

__device__ __forceinline__ float sigmoidf_fast(float x) {
    return 1.0f / (1.0f + __expf(-x));
}

__global__ void __launch_bounds__(NTHREADS) k_fused(const float* __restrict__ pred,
                                                    const float* __restrict__ target,
                                                    const float* __restrict__ jp,
                                                    float* __restrict__ out) {
    const int tid = blockIdx.x * blockDim.x + threadIdx.x;
    const int stride = GRID_BLOCKS * NTHREADS;
    const int lane = threadIdx.x & 31;

    // ---------------- main: recon + vel over pred/target (R8 body, measured best) ----------------
    float recon = 0.0f, vel = 0.0f;
    {
        const float4* p4 = (const float4*)pred;
        const float4* t4 = (const float4*)target;

        #pragma unroll
        for (int k = 0; k < MAIN_ITERS; k += 2) {
            int i0 = tid + k * stride;
            int i1 = i0 + stride;
            float4 p0 = __ldcs(p4 + i0);
            float4 t0 = __ldcs(t4 + i0);
            float4 p1 = __ldcs(p4 + i1);
            float4 t1 = __ldcs(t4 + i1);

            {
                float d0 = p0.x - t0.x, d1 = p0.y - t0.y, d2 = p0.z - t0.z, d3 = p0.w - t0.w;
                recon += d0 * d0 + d1 * d1 + d2 * d2 + d3 * d3;
                float v01 = d1 - d0, v12 = d2 - d1, v23 = d3 - d2;
                float v = v01 * v01 + v12 * v12 + v23 * v23;
                float dn = __shfl_down_sync(0xFFFFFFFFu, d0, 1);
                bool valid = (i0 & (T4 - 1)) != (T4 - 1);
                if (lane == 31 && valid) {
                    int e = i0 * 4 + 4;
                    dn = pred[e] - target[e];
                }
                if (valid) {
                    float v3n = dn - d3;
                    v += v3n * v3n;
                }
                vel += v;
            }
            {
                float d0 = p1.x - t1.x, d1 = p1.y - t1.y, d2 = p1.z - t1.z, d3 = p1.w - t1.w;
                recon += d0 * d0 + d1 * d1 + d2 * d2 + d3 * d3;
                float v01 = d1 - d0, v12 = d2 - d1, v23 = d3 - d2;
                float v = v01 * v01 + v12 * v12 + v23 * v23;
                float dn = __shfl_down_sync(0xFFFFFFFFu, d0, 1);
                bool valid = (i1 & (T4 - 1)) != (T4 - 1);
                if (lane == 31 && valid) {
                    int e = i1 * 4 + 4;
                    dn = pred[e] - target[e];
                }
                if (valid) {
                    float v3n = dn - d3;
                    v += v3n * v3n;
                }
                vel += v;
            }
        }
    }

    // ---------------- foot contact loss ----------------
    float lsum = 0.0f, csum = 0.0f;
    {
        const int foot_map[4] = {7, 8, 10, 11};
        const int nfoot = B_DIM * 4 * T4;                 // 131072 < total threads
        if (tid < nfoot) {
            int c4 = tid & (T4 - 1);
            int row = tid >> 9;
            int b = row >> 2;
            int j = foot_map[row & 3];
            const float* base = jp + ((size_t)(b * J_DIM + j) * 3) * T_DIM;
            const float* xr = base;
            const float* yr = base + T_DIM;
            const float* zr = base + 2 * T_DIM;

            int col = c4 * 4;
            float4 x = __ldcs((const float4*)xr + c4);
            float4 y = __ldcs((const float4*)yr + c4);
            float4 z = __ldcs((const float4*)zr + c4);
            bool has_next = (col + 4 < T_DIM);
            float xs[5] = {x.x, x.y, x.z, x.w, has_next ? xr[col + 4] : 0.0f};
            float ys[5] = {y.x, y.y, y.z, y.w, has_next ? yr[col + 4] : 0.0f};
            float zs[5] = {z.x, z.y, z.z, z.w, has_next ? zr[col + 4] : 0.0f};

            int kmax = has_next ? 4 : 3;
            #pragma unroll
            for (int k = 0; k < 4; k++) {
                if (k < kmax) {
                    float w0 = sigmoidf_fast((CONTACT_THRESH - ys[k])     * 20.0f);
                    float w1 = sigmoidf_fast((CONTACT_THRESH - ys[k + 1]) * 20.0f);
                    float cw = 0.5f * (w0 + w1);
                    float dx = xs[k + 1] - xs[k];
                    float dz = zs[k + 1] - zs[k];
                    lsum += (dx * dx + dz * dz) * cw;
                    csum += cw;
                }
            }
        }
    }

    // ---------------- block reduction (R8 tail, measured best) ----------------
    __shared__ float s[4][8];
    #pragma unroll
    for (int o = 16; o; o >>= 1) {
        recon += __shfl_down_sync(0xFFFFFFFFu, recon, o);
        vel   += __shfl_down_sync(0xFFFFFFFFu, vel, o);
        lsum  += __shfl_down_sync(0xFFFFFFFFu, lsum, o);
        csum  += __shfl_down_sync(0xFFFFFFFFu, csum, o);
    }
    int warp = threadIdx.x >> 5;
    if ((threadIdx.x & 31) == 0) {
        s[0][warp] = recon; s[1][warp] = vel; s[2][warp] = lsum; s[3][warp] = csum;
    }
    __syncthreads();

    if (threadIdx.x < 4) {
        float sum = 0.0f;
        #pragma unroll
        for (int w = 0; w < NTHREADS / 32; w++) sum += s[threadIdx.x][w];
        atomicAdd(&g_acc[threadIdx.x], (double)sum);
        __threadfence();
    }
    __syncthreads();

    if (threadIdx.x == 0) {
        unsigned int done = atomicAdd(&g_done, 1u);
        if (done == gridDim.x - 1) {
            const double N1 = (double)B_DIM * J_DIM * 6 * T_DIM;
            const double N2 = (double)B_DIM * J_DIM * 6 * (T_DIM - 1);
            double recon_m = g_acc[0] / N1;
            double vel_m   = g_acc[1] / N2;
            double foot_m  = g_acc[2] / (g_acc[3] + 1e-08);
            out[0] = (float)(recon_m + LAMBDA_VEL * vel_m + LAMBDA_FOOT * foot_m);
            g_acc[0] = 0.0; g_acc[1] = 0.0; g_acc[2] = 0.0; g_acc[3] = 0.0;
            g_done = 0u;
        }
    }
}

extern "C" void kernel_launch(void* const* d_in, const int* in_sizes, int n_in,
                              void* d_out, int out_size) {
    const float* pred   = (const float*)d_in[0];
    const float* target = (const float*)d_in[1];
    const float* jp     = (const float*)d_in[2];
    float* out = (float*)d_out;
    k_fused<<<GRID_BLOCKS, NTHREADS>>>(pred, target, jp, out);
}

// round 12
// speedup vs baseline: 1.2402x; 1.2402x over previous
#include <cuda_runtime.h>
#include <cuda_bf16.h>

#define B_DIM 64
#define J_DIM 24
#define T_DIM 2048
#define T4 (T_DIM / 4)
#define LAMBDA_VEL 0.2
#define LAMBDA_FOOT 0.1
#define CONTACT_THRESH 0.05f

#define GRID_BLOCKS 1152   // 1152*256 = 294912 threads; n4/threads = 16 exactly
#define NTHREADS 256
#define MAIN_ITERS 16

// accumulators: [0]=recon, [1]=vel, [2]=foot_loss, [3]=cw_sum  (zero-init, reset by last block)
__device__ double g_acc[4];
__device__ unsigned int g_done;

__device__ __forceinline__ float sigmoidf_fast(float x) {
    return 1.0f / (1.0f + __expf(-x));
}

__global__ void __launch_bounds__(NTHREADS, 8) k_fused(const float* __restrict__ pred,
                                                       const float* __restrict__ target,
                                                       const float* __restrict__ jp,
                                                       float* __restrict__ out) {
    const int tid = blockIdx.x * blockDim.x + threadIdx.x;
    const int stride = GRID_BLOCKS * NTHREADS;
    const int lane = threadIdx.x & 31;

    // ---------------- main: recon + vel over pred/target (R8 body, measured best) ----------------
    float recon = 0.0f, vel = 0.0f;
    {
        const float4* p4 = (const float4*)pred;
        const float4* t4 = (const float4*)target;

        #pragma unroll
        for (int k = 0; k < MAIN_ITERS; k += 2) {
            int i0 = tid + k * stride;
            int i1 = i0 + stride;
            float4 p0 = __ldcs(p4 + i0);
            float4 t0 = __ldcs(t4 + i0);
            float4 p1 = __ldcs(p4 + i1);
            float4 t1 = __ldcs(t4 + i1);

            {
                float d0 = p0.x - t0.x, d1 = p0.y - t0.y, d2 = p0.z - t0.z, d3 = p0.w - t0.w;
                recon += d0 * d0 + d1 * d1 + d2 * d2 + d3 * d3;
                float v01 = d1 - d0, v12 = d2 - d1, v23 = d3 - d2;
                float v = v01 * v01 + v12 * v12 + v23 * v23;
                float dn = __shfl_down_sync(0xFFFFFFFFu, d0, 1);
                bool valid = (i0 & (T4 - 1)) != (T4 - 1);
                if (lane == 31 && valid) {
                    int e = i0 * 4 + 4;
                    dn = pred[e] - target[e];
                }
                if (valid) {
                    float v3n = dn - d3;
                    v += v3n * v3n;
                }
                vel += v;
            }
            {
                float d0 = p1.x - t1.x, d1 = p1.y - t1.y, d2 = p1.z - t1.z, d3 = p1.w - t1.w;
                recon += d0 * d0 + d1 * d1 + d2 * d2 + d3 * d3;
                float v01 = d1 - d0, v12 = d2 - d1, v23 = d3 - d2;
                float v = v01 * v01 + v12 * v12 + v23 * v23;
                float dn = __shfl_down_sync(0xFFFFFFFFu, d0, 1);
                bool valid = (i1 & (T4 - 1)) != (T4 - 1);
                if (lane == 31 && valid) {
                    int e = i1 * 4 + 4;
                    dn = pred[e] - target[e];
                }
                if (valid) {
                    float v3n = dn - d3;
                    v += v3n * v3n;
                }
                vel += v;
            }
        }
    }

    // ---------------- foot contact loss (plain loads — R8 codegen) ----------------
    float lsum = 0.0f, csum = 0.0f;
    {
        const int foot_map[4] = {7, 8, 10, 11};
        const int nfoot = B_DIM * 4 * T4;                 // 131072 < total threads
        if (tid < nfoot) {
            int c4 = tid & (T4 - 1);
            int row = tid >> 9;
            int b = row >> 2;
            int j = foot_map[row & 3];
            const float* base = jp + ((size_t)(b * J_DIM + j) * 3) * T_DIM;
            const float* xr = base;
            const float* yr = base + T_DIM;
            const float* zr = base + 2 * T_DIM;

            int col = c4 * 4;
            float4 x = ((const float4*)xr)[c4];
            float4 y = ((const float4*)yr)[c4];
            float4 z = ((const float4*)zr)[c4];
            bool has_next = (col + 4 < T_DIM);
            float xs[5] = {x.x, x.y, x.z, x.w, has_next ? xr[col + 4] : 0.0f};
            float ys[5] = {y.x, y.y, y.z, y.w, has_next ? yr[col + 4] : 0.0f};
            float zs[5] = {z.x, z.y, z.z, z.w, has_next ? zr[col + 4] : 0.0f};

            int kmax = has_next ? 4 : 3;
            #pragma unroll
            for (int k = 0; k < 4; k++) {
                if (k < kmax) {
                    float w0 = sigmoidf_fast((CONTACT_THRESH - ys[k])     * 20.0f);
                    float w1 = sigmoidf_fast((CONTACT_THRESH - ys[k + 1]) * 20.0f);
                    float cw = 0.5f * (w0 + w1);
                    float dx = xs[k + 1] - xs[k];
                    float dz = zs[k + 1] - zs[k];
                    lsum += (dx * dx + dz * dz) * cw;
                    csum += cw;
                }
            }
        }
    }

    // ---------------- block reduction (R8 tail, measured best) ----------------
    __shared__ float s[4][8];
    #pragma unroll
    for (int o = 16; o; o >>= 1) {
        recon += __shfl_down_sync(0xFFFFFFFFu, recon, o);
        vel   += __shfl_down_sync(0xFFFFFFFFu, vel, o);
        lsum  += __shfl_down_sync(0xFFFFFFFFu, lsum, o);
        csum  += __shfl_down_sync(0xFFFFFFFFu, csum, o);
    }
    int warp = threadIdx.x >> 5;
    if ((threadIdx.x & 31) == 0) {
        s[0][warp] = recon; s[1][warp] = vel; s[2][warp] = lsum; s[3][warp] = csum;
    }
    __syncthreads();

    if (threadIdx.x < 4) {
        float sum = 0.0f;
        #pragma unroll
        for (int w = 0; w < NTHREADS / 32; w++) sum += s[threadIdx.x][w];
        atomicAdd(&g_acc[threadIdx.x], (double)sum);
        __threadfence();
    }
    __syncthreads();

    if (threadIdx.x == 0) {
        unsigned int done = atomicAdd(&g_done, 1u);
        if (done == gridDim.x - 1) {
            const double N1 = (double)B_DIM * J_DIM * 6 * T_DIM;
            const double N2 = (double)B_DIM * J_DIM * 6 * (T_DIM - 1);
            double recon_m = g_acc[0] / N1;
            double vel_m   = g_acc[1] / N2;
            double foot_m  = g_acc[2] / (g_acc[3] + 1e-08);
            out[0] = (float)(recon_m + LAMBDA_VEL * vel_m + LAMBDA_FOOT * foot_m);
            g_acc[0] = 0.0; g_acc[1] = 0.0; g_acc[2] = 0.0; g_acc[3] = 0.0;
            g_done = 0u;
        }
    }
}

extern "C" void kernel_launch(void* const* d_in, const int* in_sizes, int n_in,
                              void* d_out, int out_size) {
    const float* pred   = (const float*)d_in[0];
    const float* target = (const float*)d_in[1];
    const float* jp     = (const float*)d_in[2];
    float* out = (float*)d_out;
    k_fused<<<GRID_BLOCKS, NTHREADS>>>(pred, target, jp, out);
}

// round 13
// speedup vs baseline: 1.2458x; 1.0045x over previous
#include <cuda_runtime.h>
#include <cuda_bf16.h>

#define B_DIM 64
#define J_DIM 24
#define T_DIM 2048
#define T4 (T_DIM / 4)
#define LAMBDA_VEL 0.2
#define LAMBDA_FOOT 0.1
#define CONTACT_THRESH 0.05f

#define GRID_BLOCKS 576    // 576*512 = 294912 threads; n4/threads = 16 exactly
#define NTHREADS 512
#define NWARPS (NTHREADS / 32)
#define MAIN_ITERS 16

// accumulators: [0]=recon, [1]=vel, [2]=foot_loss, [3]=cw_sum  (zero-init, reset by last block)
__device__ double g_acc[4];
__device__ unsigned int g_done;

__device__ __forceinline__ float sigmoidf_fast(float x) {
    return 1.0f / (1.0f + __expf(-x));
}

__global__ void __launch_bounds__(NTHREADS, 4) k_fused(const float* __restrict__ pred,
                                                       const float* __restrict__ target,
                                                       const float* __restrict__ jp,
                                                       float* __restrict__ out) {
    const int tid = blockIdx.x * blockDim.x + threadIdx.x;
    const int stride = GRID_BLOCKS * NTHREADS;
    const int lane = threadIdx.x & 31;

    // ---------------- main: recon + vel over pred/target (R8 body, measured best) ----------------
    float recon = 0.0f, vel = 0.0f;
    {
        const float4* p4 = (const float4*)pred;
        const float4* t4 = (const float4*)target;

        #pragma unroll
        for (int k = 0; k < MAIN_ITERS; k += 2) {
            int i0 = tid + k * stride;
            int i1 = i0 + stride;
            float4 p0 = __ldcs(p4 + i0);
            float4 t0 = __ldcs(t4 + i0);
            float4 p1 = __ldcs(p4 + i1);
            float4 t1 = __ldcs(t4 + i1);

            {
                float d0 = p0.x - t0.x, d1 = p0.y - t0.y, d2 = p0.z - t0.z, d3 = p0.w - t0.w;
                recon += d0 * d0 + d1 * d1 + d2 * d2 + d3 * d3;
                float v01 = d1 - d0, v12 = d2 - d1, v23 = d3 - d2;
                float v = v01 * v01 + v12 * v12 + v23 * v23;
                float dn = __shfl_down_sync(0xFFFFFFFFu, d0, 1);
                bool valid = (i0 & (T4 - 1)) != (T4 - 1);
                if (lane == 31 && valid) {
                    int e = i0 * 4 + 4;
                    dn = pred[e] - target[e];
                }
                if (valid) {
                    float v3n = dn - d3;
                    v += v3n * v3n;
                }
                vel += v;
            }
            {
                float d0 = p1.x - t1.x, d1 = p1.y - t1.y, d2 = p1.z - t1.z, d3 = p1.w - t1.w;
                recon += d0 * d0 + d1 * d1 + d2 * d2 + d3 * d3;
                float v01 = d1 - d0, v12 = d2 - d1, v23 = d3 - d2;
                float v = v01 * v01 + v12 * v12 + v23 * v23;
                float dn = __shfl_down_sync(0xFFFFFFFFu, d0, 1);
                bool valid = (i1 & (T4 - 1)) != (T4 - 1);
                if (lane == 31 && valid) {
                    int e = i1 * 4 + 4;
                    dn = pred[e] - target[e];
                }
                if (valid) {
                    float v3n = dn - d3;
                    v += v3n * v3n;
                }
                vel += v;
            }
        }
    }

    // ---------------- foot contact loss (plain loads — R8 codegen) ----------------
    float lsum = 0.0f, csum = 0.0f;
    {
        const int foot_map[4] = {7, 8, 10, 11};
        const int nfoot = B_DIM * 4 * T4;                 // 131072 < total threads
        if (tid < nfoot) {
            int c4 = tid & (T4 - 1);
            int row = tid >> 9;
            int b = row >> 2;
            int j = foot_map[row & 3];
            const float* base = jp + ((size_t)(b * J_DIM + j) * 3) * T_DIM;
            const float* xr = base;
            const float* yr = base + T_DIM;
            const float* zr = base + 2 * T_DIM;

            int col = c4 * 4;
            float4 x = ((const float4*)xr)[c4];
            float4 y = ((const float4*)yr)[c4];
            float4 z = ((const float4*)zr)[c4];
            bool has_next = (col + 4 < T_DIM);
            float xs[5] = {x.x, x.y, x.z, x.w, has_next ? xr[col + 4] : 0.0f};
            float ys[5] = {y.x, y.y, y.z, y.w, has_next ? yr[col + 4] : 0.0f};
            float zs[5] = {z.x, z.y, z.z, z.w, has_next ? zr[col + 4] : 0.0f};

            int kmax = has_next ? 4 : 3;
            #pragma unroll
            for (int k = 0; k < 4; k++) {
                if (k < kmax) {
                    float w0 = sigmoidf_fast((CONTACT_THRESH - ys[k])     * 20.0f);
                    float w1 = sigmoidf_fast((CONTACT_THRESH - ys[k + 1]) * 20.0f);
                    float cw = 0.5f * (w0 + w1);
                    float dx = xs[k + 1] - xs[k];
                    float dz = zs[k + 1] - zs[k];
                    lsum += (dx * dx + dz * dz) * cw;
                    csum += cw;
                }
            }
        }
    }

    // ---------------- block reduction ----------------
    __shared__ float s[4][NWARPS];
    #pragma unroll
    for (int o = 16; o; o >>= 1) {
        recon += __shfl_down_sync(0xFFFFFFFFu, recon, o);
        vel   += __shfl_down_sync(0xFFFFFFFFu, vel, o);
        lsum  += __shfl_down_sync(0xFFFFFFFFu, lsum, o);
        csum  += __shfl_down_sync(0xFFFFFFFFu, csum, o);
    }
    int warp = threadIdx.x >> 5;
    if ((threadIdx.x & 31) == 0) {
        s[0][warp] = recon; s[1][warp] = vel; s[2][warp] = lsum; s[3][warp] = csum;
    }
    __syncthreads();

    if (threadIdx.x < 4) {
        float sum = 0.0f;
        #pragma unroll
        for (int w = 0; w < NWARPS; w++) sum += s[threadIdx.x][w];
        atomicAdd(&g_acc[threadIdx.x], (double)sum);
        __threadfence();
    }
    __syncthreads();

    if (threadIdx.x == 0) {
        unsigned int done = atomicAdd(&g_done, 1u);
        if (done == gridDim.x - 1) {
            const double N1 = (double)B_DIM * J_DIM * 6 * T_DIM;
            const double N2 = (double)B_DIM * J_DIM * 6 * (T_DIM - 1);
            double recon_m = g_acc[0] / N1;
            double vel_m   = g_acc[1] / N2;
            double foot_m  = g_acc[2] / (g_acc[3] + 1e-08);
            out[0] = (float)(recon_m + LAMBDA_VEL * vel_m + LAMBDA_FOOT * foot_m);
            g_acc[0] = 0.0; g_acc[1] = 0.0; g_acc[2] = 0.0; g_acc[3] = 0.0;
            g_done = 0u;
        }
    }
}

extern "C" void kernel_launch(void* const* d_in, const int* in_sizes, int n_in,
                              void* d_out, int out_size) {
    const float* pred   = (const float*)d_in[0];
    const float* target = (const float*)d_in[1];
    const float* jp     = (const float*)d_in[2];
    float* out = (float*)d_out;
    k_fused<<<GRID_BLOCKS, NTHREADS>>>(pred, target, jp, out);
}

// round 14
// speedup vs baseline: 1.3090x; 1.0507x over previous
#include <cuda_runtime.h>
#include <cuda_bf16.h>

#define B_DIM 64
#define J_DIM 24
#define T_DIM 2048
#define T4 (T_DIM / 4)
#define LAMBDA_VEL 0.2
#define LAMBDA_FOOT 0.1
#define CONTACT_THRESH 0.05f

#define GRID_BLOCKS 1152   // 1152*256 = 294912 threads; n4/threads = 16 exactly
#define NTHREADS 256
#define MAIN_ITERS 16

// accumulators: [0]=recon, [1]=vel, [2]=foot_loss, [3]=cw_sum  (zero-init, reset by last block)
__device__ double g_acc[4];
__device__ unsigned int g_done;

__device__ __forceinline__ float sigmoidf_fast(float x) {
    return 1.0f / (1.0f + __expf(-x));
}

__global__ void __launch_bounds__(NTHREADS) k_fused(const float* __restrict__ pred,
                                                    const float* __restrict__ target,
                                                    const float* __restrict__ jp,
                                                    float* __restrict__ out) {
    const int tid = blockIdx.x * blockDim.x + threadIdx.x;
    const int stride = GRID_BLOCKS * NTHREADS;
    const int lane = threadIdx.x & 31;

    // ---------------- main: recon + vel over pred/target (measured-best body) ----------------
    float recon = 0.0f, vel = 0.0f;
    {
        const float4* p4 = (const float4*)pred;
        const float4* t4 = (const float4*)target;

        #pragma unroll
        for (int k = 0; k < MAIN_ITERS; k += 2) {
            int i0 = tid + k * stride;
            int i1 = i0 + stride;
            float4 p0 = __ldcs(p4 + i0);
            float4 t0 = __ldcs(t4 + i0);
            float4 p1 = __ldcs(p4 + i1);
            float4 t1 = __ldcs(t4 + i1);

            {
                float d0 = p0.x - t0.x, d1 = p0.y - t0.y, d2 = p0.z - t0.z, d3 = p0.w - t0.w;
                recon += d0 * d0 + d1 * d1 + d2 * d2 + d3 * d3;
                float v01 = d1 - d0, v12 = d2 - d1, v23 = d3 - d2;
                float v = v01 * v01 + v12 * v12 + v23 * v23;
                float dn = __shfl_down_sync(0xFFFFFFFFu, d0, 1);
                bool valid = (i0 & (T4 - 1)) != (T4 - 1);
                if (lane == 31 && valid) {
                    int e = i0 * 4 + 4;
                    dn = pred[e] - target[e];
                }
                if (valid) {
                    float v3n = dn - d3;
                    v += v3n * v3n;
                }
                vel += v;
            }
            {
                float d0 = p1.x - t1.x, d1 = p1.y - t1.y, d2 = p1.z - t1.z, d3 = p1.w - t1.w;
                recon += d0 * d0 + d1 * d1 + d2 * d2 + d3 * d3;
                float v01 = d1 - d0, v12 = d2 - d1, v23 = d3 - d2;
                float v = v01 * v01 + v12 * v12 + v23 * v23;
                float dn = __shfl_down_sync(0xFFFFFFFFu, d0, 1);
                bool valid = (i1 & (T4 - 1)) != (T4 - 1);
                if (lane == 31 && valid) {
                    int e = i1 * 4 + 4;
                    dn = pred[e] - target[e];
                }
                if (valid) {
                    float v3n = dn - d3;
                    v += v3n * v3n;
                }
                vel += v;
            }
        }
    }

    // ---------------- foot contact loss ----------------
    float lsum = 0.0f, csum = 0.0f;
    {
        const int foot_map[4] = {7, 8, 10, 11};
        const int nfoot = B_DIM * 4 * T4;                 // 131072 < total threads
        if (tid < nfoot) {
            int c4 = tid & (T4 - 1);
            int row = tid >> 9;
            int b = row >> 2;
            int j = foot_map[row & 3];
            const float* base = jp + ((size_t)(b * J_DIM + j) * 3) * T_DIM;
            const float* xr = base;
            const float* yr = base + T_DIM;
            const float* zr = base + 2 * T_DIM;

            int col = c4 * 4;
            float4 x = ((const float4*)xr)[c4];
            float4 y = ((const float4*)yr)[c4];
            float4 z = ((const float4*)zr)[c4];
            bool has_next = (col + 4 < T_DIM);
            float xs[5] = {x.x, x.y, x.z, x.w, has_next ? xr[col + 4] : 0.0f};
            float ys[5] = {y.x, y.y, y.z, y.w, has_next ? yr[col + 4] : 0.0f};
            float zs[5] = {z.x, z.y, z.z, z.w, has_next ? zr[col + 4] : 0.0f};

            int kmax = has_next ? 4 : 3;
            #pragma unroll
            for (int k = 0; k < 4; k++) {
                if (k < kmax) {
                    float w0 = sigmoidf_fast((CONTACT_THRESH - ys[k])     * 20.0f);
                    float w1 = sigmoidf_fast((CONTACT_THRESH - ys[k + 1]) * 20.0f);
                    float cw = 0.5f * (w0 + w1);
                    float dx = xs[k + 1] - xs[k];
                    float dz = zs[k + 1] - zs[k];
                    lsum += (dx * dx + dz * dz) * cw;
                    csum += cw;
                }
            }
        }
    }

    // ---------------- block reduction ----------------
    __shared__ float s[4][8];
    #pragma unroll
    for (int o = 16; o; o >>= 1) {
        recon += __shfl_down_sync(0xFFFFFFFFu, recon, o);
        vel   += __shfl_down_sync(0xFFFFFFFFu, vel, o);
        lsum  += __shfl_down_sync(0xFFFFFFFFu, lsum, o);
        csum  += __shfl_down_sync(0xFFFFFFFFu, csum, o);
    }
    int warp = threadIdx.x >> 5;
    if ((threadIdx.x & 31) == 0) {
        s[0][warp] = recon; s[1][warp] = vel; s[2][warp] = lsum; s[3][warp] = csum;
    }
    __syncthreads();

    // threads 0-3 each own one accumulator: parallel, uncorrelated atomic targets
    if (threadIdx.x < 4) {
        float sum = 0.0f;
        #pragma unroll
        for (int w = 0; w < NTHREADS / 32; w++) sum += s[threadIdx.x][w];
        atomicAdd(&g_acc[threadIdx.x], (double)sum);
        __threadfence();
    }
    __syncthreads();

    if (threadIdx.x == 0) {
        unsigned int done = atomicAdd(&g_done, 1u);
        if (done == gridDim.x - 1) {
            const double N1 = (double)B_DIM * J_DIM * 6 * T_DIM;
            const double N2 = (double)B_DIM * J_DIM * 6 * (T_DIM - 1);
            double recon_m = g_acc[0] / N1;
            double vel_m   = g_acc[1] / N2;
            double foot_m  = g_acc[2] / (g_acc[3] + 1e-08);
            out[0] = (float)(recon_m + LAMBDA_VEL * vel_m + LAMBDA_FOOT * foot_m);
            g_acc[0] = 0.0; g_acc[1] = 0.0; g_acc[2] = 0.0; g_acc[3] = 0.0;
            g_done = 0u;
        }
    }
}

extern "C" void kernel_launch(void* const* d_in, const int* in_sizes, int n_in,
                              void* d_out, int out_size) {
    const float* pred   = (const float*)d_in[0];
    const float* target = (const float*)d_in[1];
    const float* jp     = (const float*)d_in[2];
    float* out = (float*)d_out;
    k_fused<<<GRID_BLOCKS, NTHREADS>>>(pred, target, jp, out);
}